// round 15
// baseline (speedup 1.0000x reference)
#include <cuda_runtime.h>

#define N_NODES 10000
#define D_FEAT  128
#define N_EDGES 640000
#define CAP     256   // bucket capacity (mean in-degree 64, sigma 8 -> +24 sigma)

// ---- scratch (allocation-free __device__ globals; zero-init at load) ----
// g_count is self-cleaning: k_gather zeroes each node's counter after reading
// it, so every launch (first call and graph replays) starts from all-zero.
__device__ int g_count[N_NODES];
__device__ int g_esrc[N_NODES * CAP];   // 10.24 MB bucket storage

__device__ __forceinline__ int detect_is64(const unsigned* __restrict__ a,
                                           const unsigned* __restrict__ b) {
    // int64 indices in [0,10000) have all-zero high (odd) words; for random
    // int32 indices the odds of 8 zero words is ~1e-32.
    unsigned o = a[1] | a[3] | a[5] | a[7] | b[1] | b[3] | b[5] | b[7];
    return o == 0u;
}

__device__ __forceinline__ int load_idx(const void* p, int e, int is64) {
    return is64 ? (int)((const long long*)p)[e] : ((const int*)p)[e];
}

// ---- 1: fused histogram + bucket scatter (one atomic per edge) ----
// R4-style inline loop: load/atomic/store interleaved per edge so ptxas
// pipelines the 4 independent atomic-return chains.
#define BUILD_E 4
__global__ void __launch_bounds__(256) k_build(const void* __restrict__ src,
                                               const void* __restrict__ dst) {
    int is64 = detect_is64((const unsigned*)src, (const unsigned*)dst);
    int base = (blockIdx.x * blockDim.x + threadIdx.x) * BUILD_E;
    #pragma unroll
    for (int j = 0; j < BUILD_E; j++) {
        int e = base + j;
        if (e >= N_EDGES) return;
        int d = load_idx(dst, e, is64);
        int s = load_idx(src, e, is64);
        int r = atomicAdd(&g_count[d], 1);
        if (r < CAP) g_esrc[d * CAP + r] = s;
        // r >= CAP: dropped; gather's cold fallback rescans raw edges
        // (max is idempotent, so the superset merge is correct).
    }
}

// ---- 2: gather-max, one warp per node, lane = float4 column ----
__device__ __forceinline__ float4 max4(float4 a, float4 b) {
    return make_float4(fmaxf(a.x, b.x), fmaxf(a.y, b.y),
                       fmaxf(a.z, b.z), fmaxf(a.w, b.w));
}

// Cold path, kept out of the hot kernel's register budget.
__device__ __noinline__ float4 rescan_all_edges(const float4* __restrict__ feats,
                                                const void* __restrict__ src,
                                                const void* __restrict__ dst,
                                                int node, int lane, float4 m0) {
    int is64 = detect_is64((const unsigned*)src, (const unsigned*)dst);
    for (int e0 = 0; e0 < N_EDGES; e0 += 32) {
        int e = e0 + lane;
        int dd = (e < N_EDGES) ? load_idx(dst, e, is64) : -1;
        int ss = (e < N_EDGES) ? load_idx(src, e, is64) : 0;
        unsigned mask = __ballot_sync(0xffffffffu, dd == node);
        while (mask) {
            int b = __ffs(mask) - 1;
            mask &= mask - 1;
            int s = __shfl_sync(0xffffffffu, ss, b);
            m0 = max4(m0, feats[s * 32 + lane]);
        }
    }
    return m0;
}

__global__ void __launch_bounds__(256) k_gather(const float4* __restrict__ feats,
                                                float4* __restrict__ out,
                                                const void* __restrict__ src,
                                                const void* __restrict__ dst) {
    int gid  = blockIdx.x * blockDim.x + threadIdx.x;
    int node = gid >> 5;
    int lane = gid & 31;
    if (node >= N_NODES) return;

    int deg = g_count[node];
    __syncwarp();
    if (lane == 0) g_count[node] = 0;   // self-clean for the next launch

    if (deg == 0) {   // DGL: zero in-degree -> 0
        out[node * 32 + lane] = make_float4(0.f, 0.f, 0.f, 0.f);
        return;
    }

    int cnt = deg < CAP ? deg : CAP;
    const int* bucket = &g_esrc[node * CAP];

    const float NI = -__int_as_float(0x7f800000);  // -inf
    float4 m0 = make_float4(NI, NI, NI, NI);
    float4 m1 = m0, m2 = m0, m3 = m0;

    int i = 0;
    for (; i + 3 < cnt; i += 4) {
        int s0 = bucket[i + 0];
        int s1 = bucket[i + 1];
        int s2 = bucket[i + 2];
        int s3 = bucket[i + 3];
        float4 a = feats[s0 * 32 + lane];
        float4 b = feats[s1 * 32 + lane];
        float4 c = feats[s2 * 32 + lane];
        float4 d = feats[s3 * 32 + lane];
        m0 = max4(m0, a);
        m1 = max4(m1, b);
        m2 = max4(m2, c);
        m3 = max4(m3, d);
    }
    for (; i < cnt; i++) {
        m0 = max4(m0, feats[bucket[i] * 32 + lane]);
    }

    if (deg > CAP) {   // adversarial inputs only; never taken for this dataset
        m0 = rescan_all_edges(feats, src, dst, node, lane, m0);
    }

    m0 = max4(max4(m0, m1), max4(m2, m3));
    out[node * 32 + lane] = m0;
}

extern "C" void kernel_launch(void* const* d_in, const int* in_sizes, int n_in,
                              void* d_out, int out_size) {
    const float* feats = (const float*)d_in[0];   // [10000,128] f32
    const void*  src   = d_in[1];                 // [640000] i32 or i64
    const void*  dst   = d_in[2];                 // [640000] i32 or i64
    float4* out = (float4*)d_out;

    {
        int threads_needed = (N_EDGES + BUILD_E - 1) / BUILD_E;
        k_build<<<(threads_needed + 255) / 256, 256>>>(src, dst);
    }
    {
        long long total = (long long)N_NODES * 32;
        int blocks = (int)((total + 255) / 256);
        k_gather<<<blocks, 256>>>((const float4*)feats, out, src, dst);
    }
}

// round 16
// speedup vs baseline: 1.0336x; 1.0336x over previous
#include <cuda_runtime.h>

#define N_NODES 10000
#define D_FEAT  128
#define N_EDGES 640000
#define CAP     256   // bucket capacity (mean in-degree 64, sigma 8 -> +24 sigma)

// ---- scratch (allocation-free __device__ globals; zero-init at load) ----
// g_count is self-cleaning: k_gather zeroes each node's counter after reading
// it, so every launch (first call and graph replays) starts from all-zero.
__device__ int g_count[N_NODES];
__device__ int g_esrc[N_NODES * CAP];   // 10.24 MB bucket storage

__device__ __forceinline__ int detect_is64(const unsigned* __restrict__ a,
                                           const unsigned* __restrict__ b) {
    // int64 indices in [0,10000) have all-zero high (odd) words; for random
    // int32 indices the odds of 8 zero words is ~1e-32.
    unsigned o = a[1] | a[3] | a[5] | a[7] | b[1] | b[3] | b[5] | b[7];
    return o == 0u;
}

__device__ __forceinline__ int load_idx(const void* p, int e, int is64) {
    return is64 ? (int)((const long long*)p)[e] : ((const int*)p)[e];
}

// ---- 1: fused histogram + bucket scatter (one atomic per edge) ----
// R4-style inline loop: load/atomic/store interleaved per edge so ptxas
// pipelines the 4 independent atomic-return chains.
#define BUILD_E 4
__global__ void __launch_bounds__(256) k_build(const void* __restrict__ src,
                                               const void* __restrict__ dst) {
    int is64 = detect_is64((const unsigned*)src, (const unsigned*)dst);
    int base = (blockIdx.x * blockDim.x + threadIdx.x) * BUILD_E;
    #pragma unroll
    for (int j = 0; j < BUILD_E; j++) {
        int e = base + j;
        if (e >= N_EDGES) return;
        int d = load_idx(dst, e, is64);
        int s = load_idx(src, e, is64);
        int r = atomicAdd(&g_count[d], 1);
        if (r < CAP) g_esrc[d * CAP + r] = s;
        // r >= CAP: dropped; gather's cold fallback rescans raw edges
        // (max is idempotent, so the superset merge is correct).
    }
}

// ---- 2: gather-max, one warp per node, lane = float4 column ----
__device__ __forceinline__ float4 max4(float4 a, float4 b) {
    return make_float4(fmaxf(a.x, b.x), fmaxf(a.y, b.y),
                       fmaxf(a.z, b.z), fmaxf(a.w, b.w));
}

// Cold path, kept out of the hot kernel's register budget.
__device__ __noinline__ float4 rescan_all_edges(const float4* __restrict__ feats,
                                                const void* __restrict__ src,
                                                const void* __restrict__ dst,
                                                int node, int lane, float4 m0) {
    int is64 = detect_is64((const unsigned*)src, (const unsigned*)dst);
    for (int e0 = 0; e0 < N_EDGES; e0 += 32) {
        int e = e0 + lane;
        int dd = (e < N_EDGES) ? load_idx(dst, e, is64) : -1;
        int ss = (e < N_EDGES) ? load_idx(src, e, is64) : 0;
        unsigned mask = __ballot_sync(0xffffffffu, dd == node);
        while (mask) {
            int b = __ffs(mask) - 1;
            mask &= mask - 1;
            int s = __shfl_sync(0xffffffffu, ss, b);
            m0 = max4(m0, feats[s * 32 + lane]);
        }
    }
    return m0;
}

__global__ void __launch_bounds__(256) k_gather(const float4* __restrict__ feats,
                                                float4* __restrict__ out,
                                                const void* __restrict__ src,
                                                const void* __restrict__ dst) {
    int gid  = blockIdx.x * blockDim.x + threadIdx.x;
    int node = gid >> 5;
    int lane = gid & 31;
    if (node >= N_NODES) return;

    int deg = g_count[node];
    __syncwarp();
    if (lane == 0) g_count[node] = 0;   // self-clean for the next launch

    if (deg == 0) {   // DGL: zero in-degree -> 0
        out[node * 32 + lane] = make_float4(0.f, 0.f, 0.f, 0.f);
        return;
    }

    int cnt = deg < CAP ? deg : CAP;
    const int* bucket = &g_esrc[node * CAP];

    const float NI = -__int_as_float(0x7f800000);  // -inf
    float4 m0 = make_float4(NI, NI, NI, NI);
    float4 m1 = m0, m2 = m0, m3 = m0;

    int i = 0;
    for (; i + 3 < cnt; i += 4) {
        int s0 = bucket[i + 0];
        int s1 = bucket[i + 1];
        int s2 = bucket[i + 2];
        int s3 = bucket[i + 3];
        float4 a = feats[s0 * 32 + lane];
        float4 b = feats[s1 * 32 + lane];
        float4 c = feats[s2 * 32 + lane];
        float4 d = feats[s3 * 32 + lane];
        m0 = max4(m0, a);
        m1 = max4(m1, b);
        m2 = max4(m2, c);
        m3 = max4(m3, d);
    }
    for (; i < cnt; i++) {
        m0 = max4(m0, feats[bucket[i] * 32 + lane]);
    }

    if (deg > CAP) {   // adversarial inputs only; never taken for this dataset
        m0 = rescan_all_edges(feats, src, dst, node, lane, m0);
    }

    m0 = max4(max4(m0, m1), max4(m2, m3));
    out[node * 32 + lane] = m0;
}

extern "C" void kernel_launch(void* const* d_in, const int* in_sizes, int n_in,
                              void* d_out, int out_size) {
    const float* feats = (const float*)d_in[0];   // [10000,128] f32
    const void*  src   = d_in[1];                 // [640000] i32 or i64
    const void*  dst   = d_in[2];                 // [640000] i32 or i64
    float4* out = (float4*)d_out;

    {
        int threads_needed = (N_EDGES + BUILD_E - 1) / BUILD_E;
        k_build<<<(threads_needed + 255) / 256, 256>>>(src, dst);
    }
    {
        long long total = (long long)N_NODES * 32;
        int blocks = (int)((total + 255) / 256);
        k_gather<<<blocks, 256>>>((const float4*)feats, out, src, dst);
    }
}